// round 17
// baseline (speedup 1.0000x reference)
#include <cuda_runtime.h>
#include <cuda_fp16.h>
#include <math.h>
#include <stdint.h>

// Problem constants
#define BB 8
#define DD 512
#define SS 4096
#define FF 2048

// ---------------- static scratch (no allocations allowed) ----------------
__device__ float g_y [(size_t)BB * SS * DD];      // raw residual-1 (unnormalized)
__device__ float g_h2[(size_t)BB * SS * DD];
__device__ float g_rowsum[(size_t)BB * SS];
__device__ double g_acc[32];
__device__ __half g_xh  [(size_t)BB * SS * DD];
__device__ __half g_qkh [(size_t)BB * SS * 2 * DD];
__device__ __half g_vt  [(size_t)BB * DD * SS];
__device__ __half g_sh  [(size_t)BB * SS * SS];
__device__ __half g_yh  [(size_t)BB * SS * DD];
__device__ __half g_h1h [(size_t)BB * SS * FF];
__device__ __half g_wqkT[2 * DD * DD];
__device__ __half g_wvh [DD * DD];
__device__ __half g_woT [DD * DD];
__device__ __half g_wvoT[DD * DD];
__device__ __half g_w1T [(size_t)DD * FF];
__device__ __half g_w2T [(size_t)DD * FF];

// ---------------- helpers ----------------
__device__ __forceinline__ uint32_t smem_u32(const void* p)
{
    uint32_t a;
    asm("{ .reg .u64 t; cvta.to.shared.u64 t, %1; cvt.u32.u64 %0, t; }" : "=r"(a) : "l"(p));
    return a;
}

#define CP16(d, s) asm volatile("cp.async.ca.shared.global [%0], [%1], 16;" :: "r"(d), "l"(s))
#define CPC()  asm volatile("cp.async.commit_group;" ::: "memory")
#define CPW0() asm volatile("cp.async.wait_group 0;" ::: "memory")
#define CPW1() asm volatile("cp.async.wait_group 1;" ::: "memory")

#define LDMX4(r, addr) \
    asm volatile("ldmatrix.sync.aligned.m8n8.x4.shared.b16 {%0,%1,%2,%3}, [%4];" \
        : "=r"((r)[0]), "=r"((r)[1]), "=r"((r)[2]), "=r"((r)[3]) : "r"(addr))

__device__ __forceinline__ void mma16816(float c[4], const uint32_t a[4],
                                         uint32_t b0, uint32_t b1)
{
    asm volatile(
        "mma.sync.aligned.m16n8k16.row.col.f32.f16.f16.f32 "
        "{%0,%1,%2,%3}, {%4,%5,%6,%7}, {%8,%9}, {%0,%1,%2,%3};\n"
        : "+f"(c[0]), "+f"(c[1]), "+f"(c[2]), "+f"(c[3])
        : "r"(a[0]), "r"(a[1]), "r"(a[2]), "r"(a[3]),
          "r"(b0), "r"(b1));
}

__device__ __forceinline__ uint32_t ex2_f16x2(uint32_t u)
{
    asm("ex2.approx.f16x2 %0, %0;" : "+r"(u));
    return u;
}

// ---------------- fp16 tensor-core GEMM (single batch per launch) ----------------
// 128 threads (4 warps), warp tile 64x64, CTA tile 128x128, TK=64.
// EPI: 0 none, 1 +bias, 2 relu(+bias),
//      3 normalize by rowsum[m], +residual res[N,M] (ld=SS), +stats -> fp32
//      4 +bias +normalize(res[M,N], stats0) residual +stats -> fp32
//      5 exp2 epilogue -> fp16, row sums -> atomicAdd rsum
// OUT: 0 fp32 [M,N]; 1 fp16 [M,N]; 2 fp16 transposed [N,M]
#define SKB 144
#define TILE_B (128 * SKB)
#define SMEMB (4 * TILE_B)

template <int EPI, int OUT>
__global__ __launch_bounds__(128)
void gemm_h(const __half* __restrict__ A, const __half* __restrict__ B,
            const float* __restrict__ bias, void* __restrict__ Cv,
            int K, int lda, int ldb, int ldc,
            const float* __restrict__ res,
            double* __restrict__ stats, const double* __restrict__ stats0,
            float* __restrict__ rsum, float escale)
{
    extern __shared__ char smem[];
    const uint32_t base = smem_u32(smem);

    const int m0 = blockIdx.y * 128;
    const int n0 = blockIdx.x * 128;
    const int tid  = threadIdx.x;
    const int lane = tid & 31;
    const int warp = tid >> 5;
    const int wm = (warp >> 1) * 64;
    const int wn = (warp & 1) * 64;
    const int qr = lane >> 2;
    const int qc = lane & 3;

    float acc[4][8][4];
#pragma unroll
    for (int i = 0; i < 4; i++)
#pragma unroll
        for (int j = 0; j < 8; j++)
#pragma unroll
            for (int q = 0; q < 4; q++) acc[i][j][q] = 0.f;

    const int NKB = K >> 6;

    const int sx = tid >> 3;
    const int sc = tid & 7;
    const uint32_t sdst = (uint32_t)(sx * SKB + sc * 16);

#define STAGE(buf, k0)                                                          \
    do {                                                                        \
        const uint32_t aD = base + (buf) * TILE_B + sdst;                       \
        const uint32_t bD = base + (2 + (buf)) * TILE_B + sdst;                 \
        const __half* aSrc = A + (long long)(m0 + sx) * lda + (k0) + sc * 8;    \
        const __half* bSrc = B + (long long)(n0 + sx) * ldb + (k0) + sc * 8;    \
        _Pragma("unroll")                                                       \
        for (int it = 0; it < 8; it++) {                                        \
            CP16(aD + it * (16 * SKB), aSrc + (long long)(it * 16) * lda);      \
            CP16(bD + it * (16 * SKB), bSrc + (long long)(it * 16) * ldb);      \
        }                                                                       \
    } while (0)

    STAGE(0, 0);
    CPC();

    const uint32_t aOff = (uint32_t)((wm + (lane & 15)) * SKB + (lane >> 4) * 16);
    const uint32_t bOff = (uint32_t)((wn + (lane & 15)) * SKB + (lane >> 4) * 16);

    for (int kb = 0; kb < NKB; kb++) {
        const int cur = kb & 1;
        if (kb + 1 < NKB) {
            STAGE(cur ^ 1, (kb + 1) << 6);
            CPC();
            CPW1();
        } else {
            CPW0();
        }
        __syncthreads();

        const uint32_t aT = base + cur * TILE_B + aOff;
        const uint32_t bT = base + (2 + cur) * TILE_B + bOff;
#pragma unroll
        for (int ks = 0; ks < 4; ks++) {
            uint32_t af[4][4], bq[4][4];
#pragma unroll
            for (int mi = 0; mi < 4; mi++)
                LDMX4(af[mi], aT + mi * (16 * SKB) + ks * 32);
#pragma unroll
            for (int ni = 0; ni < 4; ni++)
                LDMX4(bq[ni], bT + ni * (16 * SKB) + ks * 32);
#pragma unroll
            for (int mi = 0; mi < 4; mi++)
#pragma unroll
                for (int ni = 0; ni < 4; ni++) {
                    mma16816(acc[mi][2 * ni],     af[mi], bq[ni][0], bq[ni][2]);
                    mma16816(acc[mi][2 * ni + 1], af[mi], bq[ni][1], bq[ni][3]);
                }
        }
        __syncthreads();
    }
#undef STAGE

    // ---- epilogue ----
    float ls = 0.f, lq = 0.f;
    float nfm = 0.f, ninv = 1.f;
    if (EPI == 4) {
        const double sum = stats0[0], sq = stats0[1];
        const double NE = (double)SS * DD;
        const double mean = sum / NE;
        double var = sq - NE * mean * mean;
        if (var < 0.0) var = 0.0;
        ninv = (float)(1.0 / (sqrt(var) + 1e-7));
        nfm  = (float)mean;
    }
    float zinv0[4], zinv1[4];
    if (EPI == 3) {
#pragma unroll
        for (int mi = 0; mi < 4; mi++) {
            const int m = m0 + wm + mi * 16 + qr;
            zinv0[mi] = 1.f / rsum[m];
            zinv1[mi] = 1.f / rsum[m + 8];
        }
    }
    float rs0[4], rs1[4];
    if (EPI == 5) {
#pragma unroll
        for (int mi = 0; mi < 4; mi++) { rs0[mi] = 0.f; rs1[mi] = 0.f; }
    }

#pragma unroll
    for (int mi = 0; mi < 4; mi++) {
        const int m = m0 + wm + mi * 16 + qr;
#pragma unroll
        for (int ni = 0; ni < 8; ni++) {
            const int nc = n0 + wn + ni * 8 + 2 * qc;
            float c0 = acc[mi][ni][0], c1 = acc[mi][ni][1];
            float c2 = acc[mi][ni][2], c3 = acc[mi][ni][3];

            if (EPI == 5) {
                __half2 h01 = __floats2half2_rn(c0 * escale, c1 * escale);
                __half2 h23 = __floats2half2_rn(c2 * escale, c3 * escale);
                uint32_t u01 = ex2_f16x2(*(const uint32_t*)&h01);
                uint32_t u23 = ex2_f16x2(*(const uint32_t*)&h23);
                __half* C = (__half*)Cv;
                *(uint32_t*)(C + (long long)m * ldc + nc)       = u01;
                *(uint32_t*)(C + (long long)(m + 8) * ldc + nc) = u23;
                const float2 f01 = __half22float2(*(const __half2*)&u01);
                const float2 f23 = __half22float2(*(const __half2*)&u23);
                rs0[mi] += f01.x + f01.y;
                rs1[mi] += f23.x + f23.y;
                continue;
            }

            if (EPI == 1 || EPI == 2 || EPI == 4) {
                const float bx = bias[nc], by = bias[nc + 1];
                c0 += bx; c1 += by; c2 += bx; c3 += by;
            }
            if (EPI == 2) {
                c0 = fmaxf(c0, 0.f); c1 = fmaxf(c1, 0.f);
                c2 = fmaxf(c2, 0.f); c3 = fmaxf(c3, 0.f);
            }
            if (EPI == 3) {
                c0 = c0 * zinv0[mi] + res[(long long)nc * SS + m];
                c1 = c1 * zinv0[mi] + res[(long long)(nc + 1) * SS + m];
                c2 = c2 * zinv1[mi] + res[(long long)nc * SS + m + 8];
                c3 = c3 * zinv1[mi] + res[(long long)(nc + 1) * SS + m + 8];
            }
            if (EPI == 4) {
                const float2 r0 = *(const float2*)(res + (long long)m * DD + nc);
                const float2 r1 = *(const float2*)(res + (long long)(m + 8) * DD + nc);
                c0 += (r0.x - nfm) * ninv; c1 += (r0.y - nfm) * ninv;
                c2 += (r1.x - nfm) * ninv; c3 += (r1.y - nfm) * ninv;
            }
            if (EPI == 3 || EPI == 4) {
                ls += c0 + c1 + c2 + c3;
                lq += c0 * c0 + c1 * c1 + c2 * c2 + c3 * c3;
            }
            if (OUT == 0) {
                float* C = (float*)Cv;
                float2 lo; lo.x = c0; lo.y = c1;
                float2 hi; hi.x = c2; hi.y = c3;
                *(float2*)(C + (long long)m * ldc + nc) = lo;
                *(float2*)(C + (long long)(m + 8) * ldc + nc) = hi;
            } else if (OUT == 1) {
                __half* C = (__half*)Cv;
                *(__half2*)(C + (long long)m * ldc + nc) = __floats2half2_rn(c0, c1);
                *(__half2*)(C + (long long)(m + 8) * ldc + nc) = __floats2half2_rn(c2, c3);
            } else {
                __half* C = (__half*)Cv;
                C[(long long)nc * ldc + m]           = __float2half_rn(c0);
                C[(long long)(nc + 1) * ldc + m]     = __float2half_rn(c1);
                C[(long long)nc * ldc + m + 8]       = __float2half_rn(c2);
                C[(long long)(nc + 1) * ldc + m + 8] = __float2half_rn(c3);
            }
        }
    }

    if (EPI == 5) {
#pragma unroll
        for (int mi = 0; mi < 4; mi++) {
            float a = rs0[mi], b = rs1[mi];
            a += __shfl_xor_sync(0xFFFFFFFFu, a, 1);
            a += __shfl_xor_sync(0xFFFFFFFFu, a, 2);
            b += __shfl_xor_sync(0xFFFFFFFFu, b, 1);
            b += __shfl_xor_sync(0xFFFFFFFFu, b, 2);
            if (qc == 0) {
                const int m = m0 + wm + mi * 16 + qr;
                atomicAdd(rsum + m, a);
                atomicAdd(rsum + m + 8, b);
            }
        }
    }

    if (EPI == 3 || EPI == 4) {
        float* sa = (float*)smem;
        float* sb = sa + 128;
        sa[tid] = ls; sb[tid] = lq;
        __syncthreads();
        for (int o = 64; o > 0; o >>= 1) {
            if (tid < o) { sa[tid] += sa[tid + o]; sb[tid] += sb[tid + o]; }
            __syncthreads();
        }
        if (tid == 0) {
            atomicAdd(stats + 0, (double)sa[0]);
            atomicAdd(stats + 1, (double)sb[0]);
        }
    }
}

// ---------------- transpose + fp32->fp16 convert: src[R,C] -> dst[C,R] ----------------
__global__ void transpose_h(const float* __restrict__ src, __half* __restrict__ dst,
                            int R, int C)
{
    const int b = blockIdx.z;
    src += (long long)b * R * C;
    dst += (long long)b * R * C;
    const int r0 = blockIdx.y * 32;
    const int c0 = blockIdx.x * 32;
    __shared__ float t[32][33];
    const int tx = threadIdx.x, ty = threadIdx.y;
#pragma unroll
    for (int i = 0; i < 32; i += 8)
        t[ty + i][tx] = src[(long long)(r0 + ty + i) * C + c0 + tx];
    __syncthreads();
#pragma unroll
    for (int i = 0; i < 32; i += 8)
        dst[(long long)(c0 + ty + i) * R + r0 + tx] = __float2half_rn(t[tx][ty + i]);
}

__global__ void convert_h(const float* __restrict__ src, __half* __restrict__ dst)
{
    const long long i = (long long)blockIdx.x * 256 + threadIdx.x;
    const float4 v = ((const float4*)src)[i];
    __half2* d = (__half2*)dst + i * 2;
    d[0] = __floats2half2_rn(v.x, v.y);
    d[1] = __floats2half2_rn(v.z, v.w);
}

__global__ void zero_all_kernel(float* __restrict__ rs)
{
    const int i = blockIdx.x * 256 + threadIdx.x;
    rs[i] = 0.f;
    if (blockIdx.x == 0 && threadIdx.x < 32) g_acc[threadIdx.x] = 0.0;
}

// per-batch: read raw y, write normalized fp16 copy (grid.x = 2048)
__global__ void apply1h_kernel(const float* __restrict__ y, __half* __restrict__ yh,
                               const double* __restrict__ st)
{
    const double sum = st[0], sq = st[1];
    const double NE = (double)SS * DD;
    const double mean = sum / NE;
    double var = sq - NE * mean * mean;
    if (var < 0.0) var = 0.0;
    const float inv = (float)(1.0 / (sqrt(var) + 1e-7));
    const float fm = (float)mean;

    const float4* y4 = (const float4*)y;
    __half2* yh2 = (__half2*)yh;
    const long long i = (long long)blockIdx.x * 256 + threadIdx.x;
    float4 vv = y4[i];
    vv.x = (vv.x - fm) * inv; vv.y = (vv.y - fm) * inv;
    vv.z = (vv.z - fm) * inv; vv.w = (vv.w - fm) * inv;
    yh2[i * 2]     = __floats2half2_rn(vv.x, vv.y);
    yh2[i * 2 + 1] = __floats2half2_rn(vv.z, vv.w);
}

// per-batch: out[d,s] = (y2[s,d] - mean) * inv
__global__ void apply2t_kernel(const float* __restrict__ y2, float* __restrict__ out,
                               const double* __restrict__ st)
{
    const double sum = st[0], sq = st[1];
    const double NE = (double)SS * DD;
    const double mean = sum / NE;
    double var = sq - NE * mean * mean;
    if (var < 0.0) var = 0.0;
    const float inv = (float)(1.0 / (sqrt(var) + 1e-7));
    const float fm = (float)mean;

    const int s0 = blockIdx.x * 32;
    const int d0 = blockIdx.y * 32;
    __shared__ float ys[32][33];
    const int tx = threadIdx.x, ty = threadIdx.y;

#pragma unroll
    for (int i = 0; i < 32; i += 8)
        ys[ty + i][tx] = y2[((long long)(s0 + ty + i)) * DD + d0 + tx];
    __syncthreads();
#pragma unroll
    for (int i = 0; i < 32; i += 8)
        out[((long long)(d0 + ty + i)) * SS + s0 + tx] =
            (ys[tx][ty + i] - fm) * inv;
}

// ---------------- host-side orchestration ----------------
template <typename T>
static T* sym(const void* symbol)
{
    void* p = nullptr;
    cudaGetSymbolAddress(&p, symbol);
    return (T*)p;
}

extern "C" void kernel_launch(void* const* d_in, const int* in_sizes, int n_in,
                              void* d_out, int out_size)
{
    const float* x  = (const float*)d_in[0];
    const float* Wq = (const float*)d_in[1];
    const float* Wk = (const float*)d_in[2];
    const float* Wv = (const float*)d_in[3];
    const float* Wo = (const float*)d_in[4];
    const float* W1 = (const float*)d_in[5];
    const float* b1 = (const float*)d_in[6];
    const float* W2 = (const float*)d_in[7];
    const float* b2 = (const float*)d_in[8];
    float* out = (float*)d_out;

    float*  py    = sym<float>((const void*)g_y);
    float*  ph2   = sym<float>((const void*)g_h2);
    float*  prs   = sym<float>((const void*)g_rowsum);
    double* pacc  = sym<double>((const void*)g_acc);
    __half* pxh   = sym<__half>((const void*)g_xh);
    __half* pqkh  = sym<__half>((const void*)g_qkh);
    __half* pvt   = sym<__half>((const void*)g_vt);
    __half* psh   = sym<__half>((const void*)g_sh);
    __half* pyh   = sym<__half>((const void*)g_yh);
    __half* ph1h  = sym<__half>((const void*)g_h1h);
    __half* pwqkT = sym<__half>((const void*)g_wqkT);
    __half* pwvh  = sym<__half>((const void*)g_wvh);
    __half* pwoT  = sym<__half>((const void*)g_woT);
    __half* pwvoT = sym<__half>((const void*)g_wvoT);
    __half* pw1T  = sym<__half>((const void*)g_w1T);
    __half* pw2T  = sym<__half>((const void*)g_w2T);

    const long long sSD  = (long long)SS * DD;
    const long long sS2D = (long long)SS * 2 * DD;
    const long long sSS  = (long long)SS * SS;
    const long long sSF  = (long long)SS * FF;
    const long long sDS  = (long long)DD * SS;

    cudaFuncSetAttribute(gemm_h<0, 1>, cudaFuncAttributeMaxDynamicSharedMemorySize, SMEMB);
    cudaFuncSetAttribute(gemm_h<0, 2>, cudaFuncAttributeMaxDynamicSharedMemorySize, SMEMB);
    cudaFuncSetAttribute(gemm_h<2, 1>, cudaFuncAttributeMaxDynamicSharedMemorySize, SMEMB);
    cudaFuncSetAttribute(gemm_h<3, 0>, cudaFuncAttributeMaxDynamicSharedMemorySize, SMEMB);
    cudaFuncSetAttribute(gemm_h<4, 0>, cudaFuncAttributeMaxDynamicSharedMemorySize, SMEMB);
    cudaFuncSetAttribute(gemm_h<5, 1>, cudaFuncAttributeMaxDynamicSharedMemorySize, SMEMB);

    // R14-proven footprint: exactly 2 streams + 4 events, created once.
    static cudaStream_t s1 = nullptr, s2 = nullptr;
    static cudaEvent_t evFork = nullptr, evMain = nullptr, evWvo = nullptr, evW = nullptr;
    if (s1 == nullptr) {
        cudaStreamCreateWithFlags(&s1, cudaStreamNonBlocking);
        cudaStreamCreateWithFlags(&s2, cudaStreamNonBlocking);
        cudaEventCreateWithFlags(&evFork, cudaEventDisableTiming);
        cudaEventCreateWithFlags(&evMain, cudaEventDisableTiming);
        cudaEventCreateWithFlags(&evWvo, cudaEventDisableTiming);
        cudaEventCreateWithFlags(&evW, cudaEventDisableTiming);
    }

    dim3 tblk(32, 8);
    dim3 blk(128);
    dim3 gW(DD / 128, DD / 128, 1);
    dim3 gQKb(2 * DD / 128, SS / 128, 1);
    dim3 gNb(DD / 128, SS / 128, 1);
    dim3 gSb(SS / 128, SS / 128, 1);
    dim3 gFb(FF / 128, SS / 128, 1);

    // per-batch chain launcher
    auto chain = [&](int b, cudaStream_t st) {
        gemm_h<0, 1><<<gQKb, blk, SMEMB, st>>>(pxh + (long long)b * sSD, pwqkT,
            nullptr, pqkh + (long long)b * sS2D, DD, DD, DD, 2 * DD,
            nullptr, nullptr, nullptr, nullptr, 0.f);
        gemm_h<0, 2><<<gNb, blk, SMEMB, st>>>(pxh + (long long)b * sSD, pwvoT,
            nullptr, pvt + (long long)b * sDS, DD, DD, DD, SS,
            nullptr, nullptr, nullptr, nullptr, 0.f);
        gemm_h<5, 1><<<gSb, blk, SMEMB, st>>>(pqkh + (long long)b * sS2D,
            pqkh + (long long)b * sS2D + DD, nullptr, psh + (long long)b * sSS,
            DD, 2 * DD, 2 * DD, SS,
            nullptr, nullptr, nullptr, prs + (long long)b * SS,
            0.06375810406f /* log2(e)/sqrt(512) */);
        gemm_h<3, 0><<<gNb, blk, SMEMB, st>>>(psh + (long long)b * sSS,
            pvt + (long long)b * sDS, nullptr, py + (long long)b * sSD,
            SS, SS, SS, DD,
            x + (long long)b * sDS, pacc + 2 * b, nullptr,
            prs + (long long)b * SS, 0.f);
        apply1h_kernel<<<2048, 256, 0, st>>>(py + (long long)b * sSD,
            pyh + (long long)b * sSD, pacc + 2 * b);
        gemm_h<2, 1><<<gFb, blk, SMEMB, st>>>(pyh + (long long)b * sSD, pw1T,
            b1, ph1h + (long long)b * sSF, DD, DD, DD, FF,
            nullptr, nullptr, nullptr, nullptr, 0.f);
        gemm_h<4, 0><<<gNb, blk, SMEMB, st>>>(ph1h + (long long)b * sSF, pw2T,
            b2, ph2 + (long long)b * sSD, FF, FF, FF, DD,
            py + (long long)b * sSD, pacc + 16 + 2 * b, pacc + 2 * b,
            nullptr, 0.f);
        apply2t_kernel<<<dim3(SS / 32, DD / 32, 1), tblk, 0, st>>>(
            ph2 + (long long)b * sSD, out + (long long)b * sDS, pacc + 16 + 2 * b);
    };

    // ---- prep phase ----
    zero_all_kernel<<<BB * SS / 256, 256>>>(prs);
    cudaEventRecord(evFork, 0);

    transpose_h<<<dim3(SS / 32, DD / 32, BB), tblk>>>(x, pxh, DD, SS);
    transpose_h<<<dim3(DD / 32, DD / 32, 1), tblk>>>(Wq, pwqkT,           DD, DD);
    transpose_h<<<dim3(DD / 32, DD / 32, 1), tblk>>>(Wk, pwqkT + DD * DD, DD, DD);
    transpose_h<<<dim3(FF / 32, DD / 32, 1), tblk>>>(W1, pw1T, DD, FF);
    transpose_h<<<dim3(DD / 32, FF / 32, 1), tblk>>>(W2, pw2T, FF, DD);
    cudaEventRecord(evMain, 0);   // xh + all main-stream weights ready

    // s1: Wo/Wv prep + WvWo product (waits zero-fork; only weight inputs needed)
    cudaStreamWaitEvent(s1, evFork, 0);
    transpose_h<<<dim3(DD / 32, DD / 32, 1), tblk, 0, s1>>>(Wo, pwoT, DD, DD);
    convert_h<<<DD * DD / 1024, 256, 0, s1>>>(Wv, pwvh);
    gemm_h<0, 1><<<gW, blk, SMEMB, s1>>>(pwoT, pwvh, nullptr, pwvoT,
        DD, DD, DD, DD, nullptr, nullptr, nullptr, nullptr, 0.f);
    cudaEventRecord(evWvo, s1);   // WvWo ready

    // ---- 3 concurrent batch chains ----
    // chain on stream 0 (batches 0-2): needs WvWo from s1
    cudaStreamWaitEvent(0, evWvo, 0);
    for (int b = 0; b < 3; b++) chain(b, (cudaStream_t)0);

    // chain on s1 (batches 3-5): already ordered after WvWo; needs main prep
    cudaStreamWaitEvent(s1, evMain, 0);
    for (int b = 3; b < 6; b++) chain(b, s1);

    // chain on s2 (batches 6-7): needs main prep + WvWo
    cudaStreamWaitEvent(s2, evMain, 0);
    cudaStreamWaitEvent(s2, evWvo, 0);
    for (int b = 6; b < 8; b++) chain(b, s2);

    // ---- join: re-record events as done-markers (legal re-use in capture) ----
    cudaEventRecord(evW, s1);
    cudaEventRecord(evFork, s2);
    cudaStreamWaitEvent(0, evW, 0);
    cudaStreamWaitEvent(0, evFork, 0);

    (void)in_sizes; (void)n_in; (void)out_size;
}